// round 2
// baseline (speedup 1.0000x reference)
#include <cuda_runtime.h>
#include <math.h>

#define NB 2
#define RR 360
#define NN 100
#define SS 200
#define KXN 101
#define NPIX (NN*NN)
#define NLIG (NB*RR*2)
#define NIMG (NLIG + NB*2)

// ---------------- scratch (device globals; no allocation allowed) ----------
__device__ float  d_h1[4][9][NPIX];
__device__ float  d_feat[4][2][NPIX];          // img 0..1 receptor b, 2..3 ligand b
__device__ float2 d_G[NIMG][KXN][NN];          // row DFT: [img][kx][y]
__device__ float2 d_F[NIMG][SS][KXN];          // full fwd: [img][ky][kx]
__device__ float2 d_H[NB*RR][SS][KXN];         // after inv-ky: [b*R+r][y][kx]
__device__ unsigned int d_best[NB];
__device__ float  d_pos[NB];

__device__ __forceinline__ unsigned fenc(float f) {
    unsigned u = __float_as_uint(f);
    return (u & 0x80000000u) ? ~u : (u | 0x80000000u);
}
__device__ __forceinline__ float fdec(unsigned e) {
    unsigned u = (e & 0x80000000u) ? (e & 0x7FFFFFFFu) : ~e;
    return __uint_as_float(u);
}

// ---------------- init ------------------------------------------------------
__global__ void k_init() {
    int t = threadIdx.x;
    if (t < NB) { d_best[t] = 0u; d_pos[t] = 0.0f; }
}

// ---------------- conv1 + norm_relu (FIELDS1) -------------------------------
__global__ void k_conv1(const float* __restrict__ rec, const float* __restrict__ lig,
                        const float* __restrict__ w1) {
    int img = blockIdx.y;
    int p = blockIdx.x * blockDim.x + threadIdx.x;
    if (p >= NPIX) return;
    int y = p / NN, x = p % NN;
    const float* src = (img < NB) ? (rec + img * NPIX) : (lig + (img - NB) * NPIX);
    float acc[9];
#pragma unroll
    for (int o = 0; o < 9; o++) acc[o] = 0.0f;
#pragma unroll
    for (int ky = 0; ky < 5; ky++) {
        int iy = y + ky - 2;
        if ((unsigned)iy >= NN) continue;
#pragma unroll
        for (int kx = 0; kx < 5; kx++) {
            int ix = x + kx - 2;
            if ((unsigned)ix >= NN) continue;
            float v = __ldg(src + iy * NN + ix);
#pragma unroll
            for (int o = 0; o < 9; o++)
                acc[o] = fmaf(v, __ldg(w1 + o * 25 + ky * 5 + kx), acc[o]);
        }
    }
    // FIELDS1: (0,1),(1,2),(3,2),(5,2),(7,2)
    {
        float a = acc[0];
        float n = sqrtf(a * a + 1e-12f);
        d_h1[img][0][p] = a * (n / (n + 1e-12f));
    }
#pragma unroll
    for (int g = 0; g < 4; g++) {
        int s = 1 + 2 * g;
        float a = acc[s], b = acc[s + 1];
        float n = sqrtf(a * a + b * b + 1e-12f);
        float sc = n / (n + 1e-12f);
        d_h1[img][s][p] = a * sc;
        d_h1[img][s + 1][p] = b * sc;
    }
}

// ---------------- conv2 + norm_relu (FIELDS2) + features --------------------
__global__ void k_conv2(const float* __restrict__ w2) {
    int img = blockIdx.y;
    int p = blockIdx.x * blockDim.x + threadIdx.x;
    if (p >= NPIX) return;
    int y = p / NN, x = p % NN;
    float acc[3] = {0.f, 0.f, 0.f};
    for (int ci = 0; ci < 9; ci++) {
        const float* hp = d_h1[img][ci];
#pragma unroll
        for (int ky = 0; ky < 5; ky++) {
            int iy = y + ky - 2;
            if ((unsigned)iy >= NN) continue;
#pragma unroll
            for (int kx = 0; kx < 5; kx++) {
                int ix = x + kx - 2;
                if ((unsigned)ix >= NN) continue;
                float v = hp[iy * NN + ix];
#pragma unroll
                for (int o = 0; o < 3; o++)
                    acc[o] = fmaf(v, __ldg(w2 + ((o * 9 + ci) * 5 + ky) * 5 + kx), acc[o]);
            }
        }
    }
    float o0, o1, o2;
    {
        float a = acc[0];
        float n = sqrtf(a * a + 1e-12f);
        o0 = a * (n / (n + 1e-12f));
    }
    {
        float a = acc[1], b = acc[2];
        float n = sqrtf(a * a + b * b + 1e-12f);
        float sc = n / (n + 1e-12f);
        o1 = a * sc; o2 = b * sc;
    }
    d_feat[img][0][p] = fabsf(o0);
    d_feat[img][1][p] = sqrtf(o1 * o1 + o2 * o2 + 1e-12f);
}

// ---------------- bilinear sample -------------------------------------------
__device__ __forceinline__ float samp(const float* __restrict__ im, float yf, float xf) {
    if (yf < 0.f || yf >= 100.f || xf < 0.f || xf >= 100.f) return 0.f;
    int yc = (int)yf, xc = (int)xf;
    return im[yc * NN + xc];
}

// ---------------- rotate (fused) + row DFT ----------------------------------
// block = one image (1440 rotated ligand + 4 identity receptor)
__global__ void k_rot_rowdft() {
    __shared__ float rot[NN * 105];
    __shared__ float2 tw[200];
    int bid = blockIdx.x;
    int tid = threadIdx.x;
    for (int t = tid; t < 200; t += blockDim.x) {
        double a = 6.283185307179586477 * (double)t / 200.0;
        tw[t] = make_float2((float)cos(a), (float)sin(a));
    }
    const float* src;
    bool ident;
    float ct = 1.f, st = 0.f;
    if (bid < NLIG) {
        int c = bid & 1;
        int r = (bid >> 1) % RR;
        int b = bid / (2 * RR);
        src = d_feat[NB + b][c];
        double th = -3.14159265358979323846 + (double)r * (6.283185307179586477 / 360.0);
        ct = (float)cos(th); st = (float)sin(th);
        ident = false;
    } else {
        int i = bid - NLIG;
        src = d_feat[i >> 1][i & 1];
        ident = true;
    }
    for (int p = tid; p < NPIX; p += blockDim.x) {
        int i = p / NN, j = p % NN;
        float val;
        if (ident) {
            val = src[p];
        } else {
            float xs = (float)j - 49.5f, ys = (float)i - 49.5f;
            float xq = ct * xs + st * ys + 49.5f;
            float yq = -st * xs + ct * ys + 49.5f;
            float x0f = floorf(xq), y0f = floorf(yq);
            float wx = xq - x0f, wy = yq - y0f;
            val = samp(src, y0f, x0f) * (1.f - wy) * (1.f - wx)
                + samp(src, y0f, x0f + 1.f) * (1.f - wy) * wx
                + samp(src, y0f + 1.f, x0f) * wy * (1.f - wx)
                + samp(src, y0f + 1.f, x0f + 1.f) * wy * wx;
        }
        rot[i * 105 + j] = val;
    }
    __syncthreads();
    // G[kx][y] = sum_x rot[y][x] * exp(-2pi i kx x / 200), kx 0..100
    for (int tile = tid; tile < 26 * 25; tile += blockDim.x) {
        int kx0 = (tile % 26) * 4;
        int y0 = (tile / 26) * 4;
        float aR[4][4], aS[4][4];
#pragma unroll
        for (int j2 = 0; j2 < 4; j2++)
#pragma unroll
            for (int i2 = 0; i2 < 4; i2++) { aR[j2][i2] = 0.f; aS[j2][i2] = 0.f; }
        int idx[4] = {0, 0, 0, 0};
        for (int x = 0; x < NN; x++) {
            float2 w[4];
#pragma unroll
            for (int j2 = 0; j2 < 4; j2++) {
                w[j2] = tw[idx[j2]];
                idx[j2] += kx0 + j2;
                if (idx[j2] >= 200) idx[j2] -= 200;
            }
            float v[4];
#pragma unroll
            for (int i2 = 0; i2 < 4; i2++) v[i2] = rot[(y0 + i2) * 105 + x];
#pragma unroll
            for (int j2 = 0; j2 < 4; j2++)
#pragma unroll
                for (int i2 = 0; i2 < 4; i2++) {
                    aR[j2][i2] = fmaf(v[i2], w[j2].x, aR[j2][i2]);
                    aS[j2][i2] = fmaf(v[i2], w[j2].y, aS[j2][i2]);
                }
        }
#pragma unroll
        for (int j2 = 0; j2 < 4; j2++) {
            int kx = kx0 + j2;
            if (kx < KXN)
#pragma unroll
                for (int i2 = 0; i2 < 4; i2++)
                    d_G[bid][kx][y0 + i2] = make_float2(aR[j2][i2], -aS[j2][i2]);
        }
    }
}

// ---------------- column DFT (forward) --------------------------------------
// block = (image, kx-half). F[ky][kx] = sum_y G[kx][y] * exp(-2pi i ky y/200)
__global__ void k_coldft() {
    __shared__ float2 g[51 * 101];
    __shared__ float2 tw[200];
    int img = blockIdx.x >> 1;
    int half = blockIdx.x & 1;
    int kxg0 = half * 51;
    int kw = half ? 50 : 51;
    int tid = threadIdx.x;
    for (int t = tid; t < 200; t += blockDim.x) {
        double a = 6.283185307179586477 * (double)t / 200.0;
        tw[t] = make_float2((float)cos(a), (float)sin(a));
    }
    for (int t = tid; t < 51 * 100; t += blockDim.x) {
        int kk = t / 100, y = t % 100;
        float2 v = (kk < kw) ? d_G[img][kxg0 + kk][y] : make_float2(0.f, 0.f);
        g[kk * 101 + y] = v;
    }
    __syncthreads();
    for (int tile = tid; tile < 50 * 13; tile += blockDim.x) {
        int ky0 = (tile % 50) * 4;
        int kl0 = (tile / 50) * 4;
        float fr[4][4], fi[4][4];
#pragma unroll
        for (int i2 = 0; i2 < 4; i2++)
#pragma unroll
            for (int j2 = 0; j2 < 4; j2++) { fr[i2][j2] = 0.f; fi[i2][j2] = 0.f; }
        int idx[4] = {0, 0, 0, 0};
        for (int y = 0; y < NN; y++) {
            float2 w[4];
#pragma unroll
            for (int i2 = 0; i2 < 4; i2++) {
                w[i2] = tw[idx[i2]];
                idx[i2] += ky0 + i2;
                if (idx[i2] >= 200) idx[i2] -= 200;
            }
            float2 gv[4];
#pragma unroll
            for (int j2 = 0; j2 < 4; j2++) {
                int row = kl0 + j2; if (row > 50) row = 50;
                gv[j2] = g[row * 101 + y];
            }
#pragma unroll
            for (int i2 = 0; i2 < 4; i2++)
#pragma unroll
                for (int j2 = 0; j2 < 4; j2++) {
                    fr[i2][j2] = fmaf(gv[j2].x, w[i2].x, fr[i2][j2]);
                    fr[i2][j2] = fmaf(gv[j2].y, w[i2].y, fr[i2][j2]);
                    fi[i2][j2] = fmaf(gv[j2].y, w[i2].x, fi[i2][j2]);
                    fi[i2][j2] = fmaf(-gv[j2].x, w[i2].y, fi[i2][j2]);
                }
        }
#pragma unroll
        for (int i2 = 0; i2 < 4; i2++)
#pragma unroll
            for (int j2 = 0; j2 < 4; j2++) {
                int kl = kl0 + j2;
                if (kl < kw)
                    d_F[img][ky0 + i2][kxg0 + kl] = make_float2(fr[i2][j2], fi[i2][j2]);
            }
    }
}

// ---------------- combine spectra + inverse ky DFT --------------------------
// block = (b,r, kx-chunk of 26). H[y][kx] = sum_ky sf[ky][kx] * exp(+2pi i ky y/200)
__global__ void k_combine_invy(const float* __restrict__ wb, const float* __restrict__ wc1,
                               const float* __restrict__ wc2, const float* __restrict__ wk) {
    __shared__ float2 sf[200 * 28];
    __shared__ float2 tw[200];
    int chunk = blockIdx.x & 3;
    int imgH = blockIdx.x >> 2;
    int b = imgH / RR;
    int kx0 = chunk * 26;
    int kw = (KXN - kx0 < 26) ? (KXN - kx0) : 26;
    int tid = threadIdx.x;
    float w0 = *wb, w1v = *wc1, w2v = *wc2, w3 = *wk;
    for (int t = tid; t < 200; t += blockDim.x) {
        double a = 6.283185307179586477 * (double)t / 200.0;
        tw[t] = make_float2((float)cos(a), (float)sin(a));
    }
    int imgL0 = imgH * 2, imgL1 = imgL0 + 1;
    int imgR0 = NLIG + b * 2, imgR1 = imgR0 + 1;
    for (int e = tid; e < 200 * 28; e += blockDim.x) {
        int ky = e / 28, kxl = e % 28;
        float2 v = make_float2(0.f, 0.f);
        if (kxl < kw) {
            int kx = kx0 + kxl;
            float2 lb = d_F[imgL0][ky][kx];
            float2 lB = d_F[imgL1][ky][kx];
            float2 rb = d_F[imgR0][ky][kx];
            float2 rB = d_F[imgR1][ky][kx];
            float ur = w0 * lb.x + w1v * lB.x, ui = w0 * lb.y + w1v * lB.y;
            float vr = w2v * lb.x - w3 * lB.x, vi = w2v * lb.y - w3 * lB.y;
            v.x = rb.x * ur + rb.y * ui + rB.x * vr + rB.y * vi;
            v.y = rb.x * ui - rb.y * ur + rB.x * vi - rB.y * vr;
        }
        sf[ky * 28 + kxl] = v;
    }
    __syncthreads();
    for (int tile = tid; tile < 50 * 7; tile += blockDim.x) {
        int y0 = (tile % 50) * 4;
        int kl0 = (tile / 50) * 4;
        float hr[4][4], hi[4][4];
#pragma unroll
        for (int i2 = 0; i2 < 4; i2++)
#pragma unroll
            for (int j2 = 0; j2 < 4; j2++) { hr[i2][j2] = 0.f; hi[i2][j2] = 0.f; }
        int idx[4] = {0, 0, 0, 0};
        for (int ky = 0; ky < SS; ky++) {
            float2 w[4];
#pragma unroll
            for (int i2 = 0; i2 < 4; i2++) {
                w[i2] = tw[idx[i2]];
                idx[i2] += y0 + i2;
                if (idx[i2] >= 200) idx[i2] -= 200;
            }
            float2 s[4];
#pragma unroll
            for (int j2 = 0; j2 < 4; j2++) s[j2] = sf[ky * 28 + kl0 + j2];
#pragma unroll
            for (int i2 = 0; i2 < 4; i2++)
#pragma unroll
                for (int j2 = 0; j2 < 4; j2++) {
                    hr[i2][j2] = fmaf(s[j2].x, w[i2].x, hr[i2][j2]);
                    hr[i2][j2] = fmaf(-s[j2].y, w[i2].y, hr[i2][j2]);
                    hi[i2][j2] = fmaf(s[j2].x, w[i2].y, hi[i2][j2]);
                    hi[i2][j2] = fmaf(s[j2].y, w[i2].x, hi[i2][j2]);
                }
        }
#pragma unroll
        for (int i2 = 0; i2 < 4; i2++)
#pragma unroll
            for (int j2 = 0; j2 < 4; j2++) {
                int kl = kl0 + j2;
                if (kl < kw)
                    d_H[imgH][y0 + i2][kx0 + kl] = make_float2(hr[i2][j2], hi[i2][j2]);
            }
    }
}

// ---------------- inverse kx DFT (real out) + reduce ------------------------
// block = (b,r, y-chunk of 20)
__global__ void k_invx_reduce(const int* __restrict__ gtr, const int* __restrict__ gtt) {
    __shared__ float2 hs[20 * 102];
    __shared__ float2 tw[200];
    __shared__ float red[256];
    int yc = blockIdx.x % 10;
    int imgH = blockIdx.x / 10;
    int b = imgH / RR, r = imgH % RR;
    int ybase = yc * 20;
    int tid = threadIdx.x;
    for (int t = tid; t < 200; t += blockDim.x) {
        double a = 6.283185307179586477 * (double)t / 200.0;
        tw[t] = make_float2((float)cos(a), (float)sin(a));
    }
    for (int e = tid; e < 20 * 101; e += blockDim.x) {
        int yl = e / 101, kx = e % 101;
        hs[yl * 102 + kx] = d_H[imgH][ybase + yl][kx];
    }
    __syncthreads();
    int gr = gtr[b], t0 = gtt[2 * b], t1 = gtt[2 * b + 1];
    const float inv = 1.0f / 40000.0f;
    float lmax = -3.4e38f;
    for (int tile = tid; tile < 5 * 50; tile += blockDim.x) {
        int yl0 = (tile % 5) * 4;
        int x0 = (tile / 5) * 4;
        float s[4][4];
#pragma unroll
        for (int i2 = 0; i2 < 4; i2++) {
            float h0 = hs[(yl0 + i2) * 102 + 0].x;
            float h100 = hs[(yl0 + i2) * 102 + 100].x;
#pragma unroll
            for (int j2 = 0; j2 < 4; j2++)
                s[i2][j2] = h0 + (((x0 + j2) & 1) ? -h100 : h100);
        }
        int idx[4];
#pragma unroll
        for (int j2 = 0; j2 < 4; j2++) idx[j2] = x0 + j2;  // kx=1 start
        for (int kx = 1; kx < 100; kx++) {
            float2 w[4];
#pragma unroll
            for (int j2 = 0; j2 < 4; j2++) {
                w[j2] = tw[idx[j2]];
                idx[j2] += x0 + j2;
                if (idx[j2] >= 200) idx[j2] -= 200;
            }
#pragma unroll
            for (int i2 = 0; i2 < 4; i2++) {
                float2 h = hs[(yl0 + i2) * 102 + kx];
                float a2 = 2.f * h.x, b2 = -2.f * h.y;
#pragma unroll
                for (int j2 = 0; j2 < 4; j2++) {
                    s[i2][j2] = fmaf(a2, w[j2].x, s[i2][j2]);
                    s[i2][j2] = fmaf(b2, w[j2].y, s[i2][j2]);
                }
            }
        }
#pragma unroll
        for (int i2 = 0; i2 < 4; i2++)
#pragma unroll
            for (int j2 = 0; j2 < 4; j2++) {
                float val = s[i2][j2] * inv;
                lmax = fmaxf(lmax, val);
                int y = ybase + yl0 + i2, x = x0 + j2;
                if (r == gr && y == t0 && x == t1) d_pos[b] = val;
            }
    }
    red[tid] = lmax;
    __syncthreads();
    for (int s2 = 128; s2 > 0; s2 >>= 1) {
        if (tid < s2) red[tid] = fmaxf(red[tid], red[tid + s2]);
        __syncthreads();
    }
    if (tid == 0) atomicMax(&d_best[b], fenc(red[0]));
}

// ---------------- final loss ------------------------------------------------
__global__ void k_final(float* __restrict__ out) {
    if (threadIdx.x == 0) {
        float lp = 0.f, ln = 0.f;
        for (int b = 0; b < NB; b++) {
            float p = d_pos[b];
            lp += p + p * p;
            float m = fdec(d_best[b]);
            ln += -m + m * m;
        }
        out[0] = lp / (float)NB;
        out[1] = ln / (float)NB;
    }
}

// ---------------- launch ----------------------------------------------------
extern "C" void kernel_launch(void* const* d_in, const int* in_sizes, int n_in,
                              void* d_out, int out_size) {
    const float* rec = (const float*)d_in[0];
    const float* lig = (const float*)d_in[1];
    const float* w1 = (const float*)d_in[2];
    const float* w2 = (const float*)d_in[3];
    const float* wb = (const float*)d_in[4];
    const float* wc1 = (const float*)d_in[5];
    const float* wc2 = (const float*)d_in[6];
    const float* wk = (const float*)d_in[7];
    const int* gtr = (const int*)d_in[8];
    const int* gtt = (const int*)d_in[9];
    float* out = (float*)d_out;

    k_init<<<1, 32>>>();
    dim3 gconv((NPIX + 255) / 256, 4);
    k_conv1<<<gconv, 256>>>(rec, lig, w1);
    k_conv2<<<gconv, 256>>>(w2);
    k_rot_rowdft<<<NIMG, 256>>>();
    k_coldft<<<NIMG * 2, 256>>>();
    k_combine_invy<<<NB * RR * 4, 256>>>(wb, wc1, wc2, wk);
    k_invx_reduce<<<NB * RR * 10, 256>>>(gtr, gtt);
    k_final<<<1, 32>>>(out);
}